// round 16
// baseline (speedup 1.0000x reference)
#include <cuda_runtime.h>
#include <cuda_bf16.h>
#include <cuda_fp16.h>
#include <math.h>
#include <stdint.h>

#define D_MODEL 768
#define NUM_HEADS 12
#define DK 64
#define BATCH 2
#define SEQ 2048
#define MTOT (BATCH * SEQ)          // 4096
#define XN (MTOT * D_MODEL)         // 3145728
#define WN (D_MODEL * D_MODEL)      // 589824
#define D_QKV 2304                  // fused Q|K|V column dim

// ---------------- scratch ----------------
__device__ __half g_xh[XN];
__device__ __half g_qkvh[MTOT * D_QKV];
__device__ __half g_ah[XN];
__device__ __half g_wh[4 * WN];              // fp16-rounded weights q|k|v|o
__device__ float g_part[24 * 8 * 2 * 8192];  // split-KV partial O (unnormalized)
__device__ float g_ml[24 * 8 * 2 * 256];     // split-KV per-row (m, l)
__device__ int   g_flag[24 * 8];             // split-pair arrival counters (0-init)

// work items per (b,h): heaviest-first. {qb, kt_begin, kt_end, half(-1=light)}
__device__ const int4 g_items[24] = {
    {7,0,16,-1},{15,0,16,0},{15,16,32,1},{14,0,15,0},{14,15,30,1},{6,0,14,-1},
    {13,0,14,0},{13,14,28,1},{12,0,13,0},{12,13,26,1},{5,0,12,-1},{11,0,12,0},
    {11,12,24,1},{10,0,11,0},{10,11,22,1},{4,0,10,-1},{9,0,10,0},{9,10,20,1},
    {8,0,9,0},{8,9,18,1},{3,0,8,-1},{2,0,6,-1},{1,0,4,-1},{0,0,2,-1}
};

// ---------------- helpers ----------------
__device__ __forceinline__ uint32_t smem_u32(const void* p) {
    uint32_t a;
    asm("{ .reg .u64 t; cvta.to.shared.u64 t, %1; cvt.u32.u64 %0, t; }"
        : "=r"(a) : "l"(p));
    return a;
}
__device__ __forceinline__ void cp16(uint32_t saddr, const void* gaddr) {
    asm volatile("cp.async.cg.shared.global [%0], [%1], 16;"
                 :: "r"(saddr), "l"(gaddr) : "memory");
}
__device__ __forceinline__ void ldm4(uint32_t* r, uint32_t addr) {
    asm volatile("ldmatrix.sync.aligned.m8n8.x4.shared.b16 {%0,%1,%2,%3}, [%4];"
                 : "=r"(r[0]), "=r"(r[1]), "=r"(r[2]), "=r"(r[3]) : "r"(addr));
}
__device__ __forceinline__ void ldm4t(uint32_t* r, uint32_t addr) {
    asm volatile("ldmatrix.sync.aligned.m8n8.x4.trans.shared.b16 {%0,%1,%2,%3}, [%4];"
                 : "=r"(r[0]), "=r"(r[1]), "=r"(r[2]), "=r"(r[3]) : "r"(addr));
}
__device__ __forceinline__ void mma_f16(float* c, const uint32_t* a,
                                        uint32_t b0, uint32_t b1) {
    asm volatile(
        "mma.sync.aligned.m16n8k16.row.col.f32.f16.f16.f32 "
        "{%0,%1,%2,%3}, {%4,%5,%6,%7}, {%8,%9}, {%0,%1,%2,%3};"
        : "+f"(c[0]), "+f"(c[1]), "+f"(c[2]), "+f"(c[3])
        : "r"(a[0]), "r"(a[1]), "r"(a[2]), "r"(a[3]), "r"(b0), "r"(b1));
}
__device__ __forceinline__ uint32_t pack2h(float x, float y) {
    __half2 v(__float2half_rn(x), __float2half_rn(y));
    return *reinterpret_cast<uint32_t*>(&v);
}

// ---------------- fp32 -> fp16 round: x + 4 weights, one launch ----------------
__global__ __launch_bounds__(256)
void round5_kernel(const float* __restrict__ x,
                   const float* __restrict__ w0, const float* __restrict__ w1,
                   const float* __restrict__ w2, const float* __restrict__ w3) {
    int i = blockIdx.x * blockDim.x + threadIdx.x;
    const int seg = blockIdx.y;
    const float* src;
    __half* dst;
    int n4;
    if (seg == 0)      { src = x;  dst = g_xh;          n4 = XN / 4; }
    else if (seg == 1) { src = w0; dst = g_wh;          n4 = WN / 4; }
    else if (seg == 2) { src = w1; dst = g_wh + WN;     n4 = WN / 4; }
    else if (seg == 3) { src = w2; dst = g_wh + 2 * WN; n4 = WN / 4; }
    else               { src = w3; dst = g_wh + 3 * WN; n4 = WN / 4; }
    if (i >= n4) return;
    float4 v = reinterpret_cast<const float4*>(src)[i];
    reinterpret_cast<uint2*>(dst)[i] =
        make_uint2(pack2h(v.x, v.y), pack2h(v.z, v.w));
}

// ---------------- fp16 NT GEMM, 128x128 tile, BK=64, 1 product ----------------
#define PITCHG 144
#define GBM 128
#define GBN 128
#define G_OFF_BH (GBM * PITCHG)
#define G_STAGE ((GBM + GBN) * PITCHG)     // 36864
#define GEMM_SMEM (3 * G_STAGE)            // 110592

__device__ __forceinline__ void wait_rem(int rem) {
    if (rem >= 2)      asm volatile("cp.async.wait_group 2;" ::: "memory");
    else if (rem == 1) asm volatile("cp.async.wait_group 1;" ::: "memory");
    else               asm volatile("cp.async.wait_group 0;" ::: "memory");
}

__device__ __forceinline__ void load_stage(
    uint32_t sbase, const __half* Ah, const __half* Bh,
    int m0, int n0, int k0, int K, int tid) {
    #pragma unroll
    for (int l = 0; l < 4; l++) {               // A: 128 rows x 8 x 16B
        int idx = tid + l * 256;
        int r = idx >> 3;
        int c = idx & 7;
        uint32_t so = (uint32_t)(r * PITCHG + c * 16);
        cp16(sbase + so, Ah + (size_t)(m0 + r) * K + k0 + c * 8);
    }
    #pragma unroll
    for (int l = 0; l < 4; l++) {               // B: 128 rows x 8 x 16B
        int idx = tid + l * 256;
        int r = idx >> 3;
        int c = idx & 7;
        uint32_t so = (uint32_t)(r * PITCHG + c * 16);
        cp16(sbase + G_OFF_BH + so, Bh + (size_t)(n0 + r) * K + k0 + c * 8);
    }
    asm volatile("cp.async.commit_group;" ::: "memory");
}

template<bool SPLIT_OUT>
__global__ __launch_bounds__(256, 2)
void gemm_mma(const __half* __restrict__ Ah, const __half* __restrict__ Bh,
              float* __restrict__ C, __half* __restrict__ Ch,
              int M, int N, int K) {
    extern __shared__ char smc[];
    const uint32_t sb = smem_u32(smc);
    const int tid = threadIdx.x;
    const int lane = tid & 31;
    const int wid = tid >> 5;
    const int wm = (wid & 3) * 32;
    const int wn = (wid >> 2) * 64;
    const int m0 = blockIdx.y * GBM;
    const int n0 = blockIdx.x * GBN;

    float acc[2][8][4] = {};
    const int a_lr = lane & 15, a_lc = lane >> 4;
    const int b_lr = lane & 7, b_kh = (lane >> 3) & 1, b_nh = lane >> 4;

    const int nstage = K / 64;   // 12
    load_stage(sb, Ah, Bh, m0, n0, 0, K, tid);
    if (nstage > 1)
        load_stage(sb + G_STAGE, Ah, Bh, m0, n0, 64, K, tid);

    for (int kt = 0; kt < nstage; kt++) {
        if (kt + 2 < nstage)
            load_stage(sb + (uint32_t)((kt + 2) % 3) * G_STAGE,
                       Ah, Bh, m0, n0, (kt + 2) * 64, K, tid);
        wait_rem(nstage - kt - 1);
        __syncthreads();

        const uint32_t st = sb + (uint32_t)(kt % 3) * G_STAGE;
        #pragma unroll
        for (int kk = 0; kk < 4; kk++) {
            const uint32_t kcol = (uint32_t)((kk * 16 + a_lc * 8) * 2);
            uint32_t ah[2][4];
            #pragma unroll
            for (int mi = 0; mi < 2; mi++)
                ldm4(ah[mi], st + (uint32_t)((wm + mi * 16 + a_lr) * PITCHG) + kcol);
            const uint32_t bkcol = (uint32_t)((kk * 16 + b_kh * 8) * 2);
            uint32_t bh[4][4];
            #pragma unroll
            for (int ni = 0; ni < 4; ni++) {
                uint32_t ro = (uint32_t)((wn + ni * 16 + b_lr + b_nh * 8) * PITCHG) + bkcol;
                ldm4(bh[ni], st + G_OFF_BH + ro);
            }
            #pragma unroll
            for (int mi = 0; mi < 2; mi++)
                #pragma unroll
                for (int nj = 0; nj < 8; nj++) {
                    const int ni = nj >> 1, od = (nj & 1) * 2;
                    mma_f16(acc[mi][nj], ah[mi], bh[ni][od], bh[ni][od + 1]);
                }
        }
        __syncthreads();
    }

    const int g = lane >> 2, t = lane & 3;
    const float sc = (SPLIT_OUT && n0 < 768) ? 0.180336880111112f : 1.0f;
    #pragma unroll
    for (int mi = 0; mi < 2; mi++)
        #pragma unroll
        for (int nj = 0; nj < 8; nj++) {
            int row = m0 + wm + mi * 16 + g;
            int col = n0 + wn + nj * 8 + t * 2;
            if (SPLIT_OUT) {
                *reinterpret_cast<uint32_t*>(&Ch[(size_t)row * N + col]) =
                    pack2h(acc[mi][nj][0] * sc, acc[mi][nj][1] * sc);
                *reinterpret_cast<uint32_t*>(&Ch[(size_t)(row + 8) * N + col]) =
                    pack2h(acc[mi][nj][2] * sc, acc[mi][nj][3] * sc);
            } else {
                *reinterpret_cast<float2*>(&C[(size_t)row * N + col]) =
                    make_float2(acc[mi][nj][0], acc[mi][nj][1]);
                *reinterpret_cast<float2*>(&C[(size_t)(row + 8) * N + col]) =
                    make_float2(acc[mi][nj][2], acc[mi][nj][3]);
            }
        }
}

// ---------------- fp16 causal flash attention, split-KV + fused combine ----------
// S = Qh*Kh (1 product), Q pre-scaled by 0.125*log2(e); exp2 softmax;
// O = Ph*Vh (1 product). grid (24 bh, 24 items), 4 KV buffers, 1 barrier/tile.
// Split pairs merge in-kernel: second-arriving CTA (atomic counter) does the
// deterministic fp32 merge and resets the flag (self-resetting across replays).
#define P144 144
#define SQH 0
#define SKV 18432
#define KVSTAGE 18432          // KH 0 | VH 9216
#define ATT_SMEM (SKV + 4 * KVSTAGE)   // 92160

__global__ __launch_bounds__(256, 2)
void attn_mma() {
    extern __shared__ char smc[];
    const uint32_t sb = smem_u32(smc);
    const int tid = threadIdx.x;
    const int lane = tid & 31;
    const int wid = tid >> 5;
    const int bh = blockIdx.x;
    const int4 it = g_items[blockIdx.y];
    const int qb = it.x, kt0 = it.y, kt1 = it.z, hlf = it.w;
    const int b = bh / NUM_HEADS;
    const int h = bh % NUM_HEADS;
    const int wm = wid * 16;
    const int g = lane >> 2, t = lane & 3;

    const size_t qrow0 = (size_t)b * SEQ + (size_t)qb * 128;
    const size_t krow0 = (size_t)b * SEQ;
    const size_t qoff = (size_t)h * DK;
    const size_t koff = 768 + (size_t)h * DK;
    const size_t voff = 1536 + (size_t)h * DK;

    // Q tile (hi fp16), persistent
    #pragma unroll
    for (int l = 0; l < 4; l++) {
        int idx = tid + l * 256;
        int r = idx >> 3, c = idx & 7;
        size_t ga = (qrow0 + r) * D_QKV + qoff + c * 8;
        uint32_t so = (uint32_t)(r * P144 + c * 16);
        cp16(sb + SQH + so, g_qkvh + ga);
    }

    const int ntl = kt1 - kt0;
    auto load_kv = [&](int kt) {
        uint32_t stb = sb + SKV + (uint32_t)(kt & 3) * KVSTAGE;
        #pragma unroll
        for (int l = 0; l < 2; l++) {
            int idx = tid + l * 256;
            int r = idx >> 3, c = idx & 7;
            size_t grow = (krow0 + (size_t)kt * 64 + r) * D_QKV;
            uint32_t so = (uint32_t)(r * P144 + c * 16);
            cp16(stb + so, g_qkvh + grow + koff + c * 8);
            cp16(stb + 9216 + so, g_qkvh + grow + voff + c * 8);
        }
        asm volatile("cp.async.commit_group;" ::: "memory");
    };

    load_kv(kt0);
    if (ntl > 1) load_kv(kt0 + 1);
    if (ntl > 2) load_kv(kt0 + 2);

    float oacc[8][4] = {};
    float m_i[2] = {-INFINITY, -INFINITY};
    float l_i[2] = {0.0f, 0.0f};

    const int a_lr = lane & 15, a_lc = lane >> 4;
    const int b_lr = lane & 7, b_kh = (lane >> 3) & 1, b_nh = lane >> 4;
    const int v_r = lane & 15, v_c = (lane >> 4) * 8;

    for (int j = 0; j < ntl; j++) {
        const int kt = kt0 + j;
        int rem = ntl - 1 - j;
        wait_rem(rem < 2 ? rem : 2);
        __syncthreads();
        if (j + 3 < ntl) load_kv(kt + 3);

        const uint32_t stb = sb + SKV + (uint32_t)(kt & 3) * KVSTAGE;
        const bool skip = (kt == 2 * qb + 1) && (wid < 4);

        if (!skip) {
            float sacc[8][4] = {};
            #pragma unroll
            for (int kk = 0; kk < 4; kk++) {
                const uint32_t kcol = (uint32_t)((kk * 16 + a_lc * 8) * 2);
                uint32_t qh[4];
                ldm4(qh, sb + SQH + (uint32_t)((wm + a_lr) * P144) + kcol);
                const uint32_t bkcol = (uint32_t)((kk * 16 + b_kh * 8) * 2);
                #pragma unroll
                for (int np = 0; np < 4; np++) {
                    uint32_t kh[4];
                    ldm4(kh, stb + (uint32_t)((np * 16 + b_lr + b_nh * 8) * P144) + bkcol);
                    mma_f16(sacc[2 * np],     qh, kh[0], kh[1]);
                    mma_f16(sacc[2 * np + 1], qh, kh[2], kh[3]);
                }
            }

            const bool needmask = (kt == 2 * qb && wid < 4) ||
                                  (kt == 2 * qb + 1 && wid >= 4);
            if (needmask) {
                const int grow0 = qb * 128 + wm + g;
                #pragma unroll
                for (int nt = 0; nt < 8; nt++) {
                    const int gcol = kt * 64 + nt * 8 + t * 2;
                    #pragma unroll
                    for (int jj = 0; jj < 4; jj++) {
                        const int row = grow0 + (jj >> 1) * 8;
                        const int col = gcol + (jj & 1);
                        if (col > row) sacc[nt][jj] = -INFINITY;
                    }
                }
            }

            #pragma unroll
            for (int hh = 0; hh < 2; hh++) {
                float rm = -INFINITY;
                #pragma unroll
                for (int nt = 0; nt < 8; nt++)
                    rm = fmaxf(rm, fmaxf(sacc[nt][2 * hh], sacc[nt][2 * hh + 1]));
                rm = fmaxf(rm, __shfl_xor_sync(0xffffffffu, rm, 1));
                rm = fmaxf(rm, __shfl_xor_sync(0xffffffffu, rm, 2));
                float mn = fmaxf(m_i[hh], rm);
                float alpha = exp2f(m_i[hh] - mn);
                float rs = 0.0f;
                #pragma unroll
                for (int nt = 0; nt < 8; nt++) {
                    float p0 = exp2f(sacc[nt][2 * hh] - mn);
                    float p1 = exp2f(sacc[nt][2 * hh + 1] - mn);
                    sacc[nt][2 * hh] = p0;
                    sacc[nt][2 * hh + 1] = p1;
                    rs += p0 + p1;
                }
                rs += __shfl_xor_sync(0xffffffffu, rs, 1);
                rs += __shfl_xor_sync(0xffffffffu, rs, 2);
                l_i[hh] = l_i[hh] * alpha + rs;
                m_i[hh] = mn;
                #pragma unroll
                for (int nt = 0; nt < 8; nt++) {
                    oacc[nt][2 * hh] *= alpha;
                    oacc[nt][2 * hh + 1] *= alpha;
                }
            }

            #pragma unroll
            for (int ks = 0; ks < 4; ks++) {
                uint32_t ph[4];
                ph[0] = pack2h(sacc[2 * ks][0],     sacc[2 * ks][1]);
                ph[1] = pack2h(sacc[2 * ks][2],     sacc[2 * ks][3]);
                ph[2] = pack2h(sacc[2 * ks + 1][0], sacc[2 * ks + 1][1]);
                ph[3] = pack2h(sacc[2 * ks + 1][2], sacc[2 * ks + 1][3]);
                const uint32_t vrow = (uint32_t)((ks * 16 + v_r) * P144);
                #pragma unroll
                for (int np = 0; np < 4; np++) {
                    uint32_t vh[4];
                    ldm4t(vh, stb + 9216 + vrow + (uint32_t)((np * 16 + v_c) * 2));
                    mma_f16(oacc[2 * np],     ph, vh[0], vh[1]);
                    mma_f16(oacc[2 * np + 1], ph, vh[2], vh[3]);
                }
            }
        }
    }

    const int r0 = wm + g, r1 = wm + g + 8;
    if (hlf < 0) {
        // light item: normalize + write fp16 final
        const float inv0 = 1.0f / l_i[0], inv1 = 1.0f / l_i[1];
        #pragma unroll
        for (int nt = 0; nt < 8; nt++) {
            size_t a0 = (qrow0 + r0) * D_MODEL + qoff + nt * 8 + t * 2;
            size_t a1 = (qrow0 + r1) * D_MODEL + qoff + nt * 8 + t * 2;
            *reinterpret_cast<uint32_t*>(&g_ah[a0]) =
                pack2h(oacc[nt][0] * inv0, oacc[nt][1] * inv0);
            *reinterpret_cast<uint32_t*>(&g_ah[a1]) =
                pack2h(oacc[nt][2] * inv1, oacc[nt][3] * inv1);
        }
        return;
    }

    // ---- split item: write unnormalized partial O + (m, l) ----
    const int pair = bh * 8 + (qb - 8);
    const int sidx = pair * 2 + hlf;
    float* P = g_part + (size_t)sidx * 8192;
    #pragma unroll
    for (int nt = 0; nt < 8; nt++) {
        const int col = nt * 8 + t * 2;
        *reinterpret_cast<float2*>(&P[r0 * 64 + col]) =
            make_float2(oacc[nt][0], oacc[nt][1]);
        *reinterpret_cast<float2*>(&P[r1 * 64 + col]) =
            make_float2(oacc[nt][2], oacc[nt][3]);
    }
    if (t == 0) {
        g_ml[sidx * 256 + r0 * 2 + 0] = m_i[0];
        g_ml[sidx * 256 + r0 * 2 + 1] = l_i[0];
        g_ml[sidx * 256 + r1 * 2 + 0] = m_i[1];
        g_ml[sidx * 256 + r1 * 2 + 1] = l_i[1];
    }

    // ---- fused combine: second-arriving CTA of the pair merges ----
    __threadfence();            // publish this CTA's partials
    __syncthreads();            // all threads' stores issued before the flag
    __shared__ int s_old;
    if (tid == 0) s_old = atomicAdd(&g_flag[pair], 1);
    __syncthreads();
    if (s_old == 1) {
        __threadfence();        // order flag-read before partial reads
        const int row = tid >> 1;               // 0..127
        const int c0 = (tid & 1) * 32;
        const int s0 = pair * 2;
        const float* P0 = g_part + (size_t)s0 * 8192;
        const float* P1 = P0 + 8192;
        const float m0 = g_ml[s0 * 256 + row * 2 + 0];
        const float l0 = g_ml[s0 * 256 + row * 2 + 1];
        const float m1 = g_ml[(s0 + 1) * 256 + row * 2 + 0];
        const float l1 = g_ml[(s0 + 1) * 256 + row * 2 + 1];
        const float mm = fmaxf(m0, m1);
        const float w0 = exp2f(m0 - mm), w1 = exp2f(m1 - mm);
        const float inv = 1.0f / (l0 * w0 + l1 * w1);
        const size_t orow = (qrow0 + row) * D_MODEL + qoff + c0;
        #pragma unroll
        for (int cc = 0; cc < 32; cc += 4) {
            float4 p0 = *reinterpret_cast<const float4*>(&P0[row * 64 + c0 + cc]);
            float4 p1 = *reinterpret_cast<const float4*>(&P1[row * 64 + c0 + cc]);
            uint2 o;
            o.x = pack2h((p0.x * w0 + p1.x * w1) * inv, (p0.y * w0 + p1.y * w1) * inv);
            o.y = pack2h((p0.z * w0 + p1.z * w1) * inv, (p0.w * w0 + p1.w * w1) * inv);
            *reinterpret_cast<uint2*>(&g_ah[orow + cc]) = o;
        }
        __syncthreads();
        if (tid == 0) g_flag[pair] = 0;   // reset for next graph replay
    }
}

// ---------------- launch ----------------
extern "C" void kernel_launch(void* const* d_in, const int* in_sizes, int n_in,
                              void* d_out, int out_size) {
    const float* x  = (const float*)d_in[0];
    const float* wq = (const float*)d_in[1];
    const float* wk = (const float*)d_in[2];
    const float* wv = (const float*)d_in[3];
    const float* wo = (const float*)d_in[4];
    float* out = (float*)d_out;

    __half *xh, *qkvh, *ah, *wh;
    cudaGetSymbolAddress((void**)&xh, g_xh);
    cudaGetSymbolAddress((void**)&qkvh, g_qkvh);
    cudaGetSymbolAddress((void**)&ah, g_ah);
    cudaGetSymbolAddress((void**)&wh, g_wh);

    // 1. round x + 4 weights to fp16, ONE launch
    dim3 rgrid((XN / 4 + 255) / 256, 5);
    round5_kernel<<<rgrid, 256>>>(x, wq, wk, wv, wo);

    // 2. fused QKV projection (N = 2304), BK=64, 128x128, 2 CTAs/SM
    cudaFuncSetAttribute((const void*)gemm_mma<true>,
                         cudaFuncAttributeMaxDynamicSharedMemorySize, GEMM_SMEM);
    cudaFuncSetAttribute((const void*)gemm_mma<false>,
                         cudaFuncAttributeMaxDynamicSharedMemorySize, GEMM_SMEM);
    dim3 qkvgrid(D_QKV / GBN, MTOT / GBM);   // (18, 32)
    gemm_mma<true><<<qkvgrid, 256, GEMM_SMEM>>>(xh, wh, nullptr, qkvh,
                                                MTOT, D_QKV, D_MODEL);

    // 3. split-KV flash attention with FUSED combine (no separate kernel)
    cudaFuncSetAttribute(attn_mma, cudaFuncAttributeMaxDynamicSharedMemorySize, ATT_SMEM);
    dim3 agrid(24, 24);   // x = bh, y = work item (heaviest first)
    attn_mma<<<agrid, 256, ATT_SMEM>>>();

    // 4. output projection -> fp32 (1 product), 128x128 tiles
    dim3 ogrid(D_MODEL / GBN, MTOT / GBM);   // (6, 32)
    gemm_mma<false><<<ogrid, 256, GEMM_SMEM>>>(ah, wh + 3 * WN, out, nullptr,
                                               MTOT, D_MODEL, D_MODEL);
}

// round 17
// speedup vs baseline: 1.0847x; 1.0847x over previous
#include <cuda_runtime.h>
#include <cuda_bf16.h>
#include <cuda_fp16.h>
#include <math.h>
#include <stdint.h>

#define D_MODEL 768
#define NUM_HEADS 12
#define DK 64
#define BATCH 2
#define SEQ 2048
#define MTOT (BATCH * SEQ)          // 4096
#define XN (MTOT * D_MODEL)         // 3145728
#define WN (D_MODEL * D_MODEL)      // 589824
#define D_QKV 2304                  // fused Q|K|V column dim

// ---------------- scratch ----------------
__device__ __half g_xh[XN];
__device__ __half g_qkvh[MTOT * D_QKV];
__device__ __half g_ah[XN];
__device__ __half g_wh[4 * WN];              // fp16-rounded weights q|k|v|o
__device__ float g_part[24 * 8 * 2 * 8192];  // split-KV partial O (unnormalized)
__device__ float g_ml[24 * 8 * 2 * 256];     // split-KV per-row (m, l)

// work items per (b,h): heaviest-first. {qb, kt_begin, kt_end, half(-1=light)}
__device__ const int4 g_items[24] = {
    {7,0,16,-1},{15,0,16,0},{15,16,32,1},{14,0,15,0},{14,15,30,1},{6,0,14,-1},
    {13,0,14,0},{13,14,28,1},{12,0,13,0},{12,13,26,1},{5,0,12,-1},{11,0,12,0},
    {11,12,24,1},{10,0,11,0},{10,11,22,1},{4,0,10,-1},{9,0,10,0},{9,10,20,1},
    {8,0,9,0},{8,9,18,1},{3,0,8,-1},{2,0,6,-1},{1,0,4,-1},{0,0,2,-1}
};

// ---------------- helpers ----------------
__device__ __forceinline__ uint32_t smem_u32(const void* p) {
    uint32_t a;
    asm("{ .reg .u64 t; cvta.to.shared.u64 t, %1; cvt.u32.u64 %0, t; }"
        : "=r"(a) : "l"(p));
    return a;
}
__device__ __forceinline__ void cp16(uint32_t saddr, const void* gaddr) {
    asm volatile("cp.async.cg.shared.global [%0], [%1], 16;"
                 :: "r"(saddr), "l"(gaddr) : "memory");
}
__device__ __forceinline__ void ldm4(uint32_t* r, uint32_t addr) {
    asm volatile("ldmatrix.sync.aligned.m8n8.x4.shared.b16 {%0,%1,%2,%3}, [%4];"
                 : "=r"(r[0]), "=r"(r[1]), "=r"(r[2]), "=r"(r[3]) : "r"(addr));
}
__device__ __forceinline__ void ldm4t(uint32_t* r, uint32_t addr) {
    asm volatile("ldmatrix.sync.aligned.m8n8.x4.trans.shared.b16 {%0,%1,%2,%3}, [%4];"
                 : "=r"(r[0]), "=r"(r[1]), "=r"(r[2]), "=r"(r[3]) : "r"(addr));
}
__device__ __forceinline__ void mma_f16(float* c, const uint32_t* a,
                                        uint32_t b0, uint32_t b1) {
    asm volatile(
        "mma.sync.aligned.m16n8k16.row.col.f32.f16.f16.f32 "
        "{%0,%1,%2,%3}, {%4,%5,%6,%7}, {%8,%9}, {%0,%1,%2,%3};"
        : "+f"(c[0]), "+f"(c[1]), "+f"(c[2]), "+f"(c[3])
        : "r"(a[0]), "r"(a[1]), "r"(a[2]), "r"(a[3]), "r"(b0), "r"(b1));
}
__device__ __forceinline__ uint32_t pack2h(float x, float y) {
    __half2 v(__float2half_rn(x), __float2half_rn(y));
    return *reinterpret_cast<uint32_t*>(&v);
}

// ---------------- fp32 -> fp16 round: x + 4 weights, one launch ----------------
__global__ __launch_bounds__(256)
void round5_kernel(const float* __restrict__ x,
                   const float* __restrict__ w0, const float* __restrict__ w1,
                   const float* __restrict__ w2, const float* __restrict__ w3) {
    int i = blockIdx.x * blockDim.x + threadIdx.x;
    const int seg = blockIdx.y;
    const float* src;
    __half* dst;
    int n4;
    if (seg == 0)      { src = x;  dst = g_xh;          n4 = XN / 4; }
    else if (seg == 1) { src = w0; dst = g_wh;          n4 = WN / 4; }
    else if (seg == 2) { src = w1; dst = g_wh + WN;     n4 = WN / 4; }
    else if (seg == 3) { src = w2; dst = g_wh + 2 * WN; n4 = WN / 4; }
    else               { src = w3; dst = g_wh + 3 * WN; n4 = WN / 4; }
    if (i >= n4) return;
    float4 v = reinterpret_cast<const float4*>(src)[i];
    reinterpret_cast<uint2*>(dst)[i] =
        make_uint2(pack2h(v.x, v.y), pack2h(v.z, v.w));
}

// ---------------- fp16 NT GEMM, 128xTBN tile, BK=64, 1 product ----------------
// 8 warps (4 in M x 2 in N), warp tile 32 x (TBN/2). 3-stage cp.async, pitch 144.
#define PITCHG 144
#define GBM 128

__device__ __forceinline__ void wait_rem(int rem) {
    if (rem >= 2)      asm volatile("cp.async.wait_group 2;" ::: "memory");
    else if (rem == 1) asm volatile("cp.async.wait_group 1;" ::: "memory");
    else               asm volatile("cp.async.wait_group 0;" ::: "memory");
}

template<int TBN>
__device__ __forceinline__ void load_stage(
    uint32_t sbase, const __half* Ah, const __half* Bh,
    int m0, int n0, int k0, int K, int tid) {
    constexpr int OFF_BH = GBM * PITCHG;
    #pragma unroll
    for (int l = 0; l < 4; l++) {               // A: 128 rows x 8 x 16B
        int idx = tid + l * 256;
        int r = idx >> 3;
        int c = idx & 7;
        uint32_t so = (uint32_t)(r * PITCHG + c * 16);
        cp16(sbase + so, Ah + (size_t)(m0 + r) * K + k0 + c * 8);
    }
    #pragma unroll
    for (int l = 0; l < TBN / 32; l++) {        // B: TBN rows x 8 x 16B
        int idx = tid + l * 256;
        int r = idx >> 3;
        int c = idx & 7;
        uint32_t so = (uint32_t)(r * PITCHG + c * 16);
        cp16(sbase + OFF_BH + so, Bh + (size_t)(n0 + r) * K + k0 + c * 8);
    }
    asm volatile("cp.async.commit_group;" ::: "memory");
}

template<int TBN, bool SPLIT_OUT>
__global__ __launch_bounds__(256, 2)
void gemm_mma(const __half* __restrict__ Ah, const __half* __restrict__ Bh,
              float* __restrict__ C, __half* __restrict__ Ch,
              int M, int N, int K) {
    constexpr int NJ = TBN / 16;          // n-frags per warp (8-col each)
    constexpr int NB = TBN / 32;          // 16-col B-frag groups per warp
    constexpr int STAGE = (GBM + TBN) * PITCHG;
    constexpr int OFF_BH = GBM * PITCHG;
    extern __shared__ char smc[];
    const uint32_t sb = smem_u32(smc);
    const int tid = threadIdx.x;
    const int lane = tid & 31;
    const int wid = tid >> 5;
    const int wm = (wid & 3) * 32;
    const int wn = (wid >> 2) * (TBN / 2);
    const int m0 = blockIdx.y * GBM;
    const int n0 = blockIdx.x * TBN;

    float acc[2][NJ][4] = {};
    const int a_lr = lane & 15, a_lc = lane >> 4;
    const int b_lr = lane & 7, b_kh = (lane >> 3) & 1, b_nh = lane >> 4;

    const int nstage = K / 64;   // 12
    load_stage<TBN>(sb, Ah, Bh, m0, n0, 0, K, tid);
    if (nstage > 1)
        load_stage<TBN>(sb + STAGE, Ah, Bh, m0, n0, 64, K, tid);

    for (int kt = 0; kt < nstage; kt++) {
        if (kt + 2 < nstage)
            load_stage<TBN>(sb + (uint32_t)((kt + 2) % 3) * STAGE,
                            Ah, Bh, m0, n0, (kt + 2) * 64, K, tid);
        wait_rem(nstage - kt - 1);
        __syncthreads();

        const uint32_t st = sb + (uint32_t)(kt % 3) * STAGE;
        #pragma unroll
        for (int kk = 0; kk < 4; kk++) {
            const uint32_t kcol = (uint32_t)((kk * 16 + a_lc * 8) * 2);
            uint32_t ah[2][4];
            #pragma unroll
            for (int mi = 0; mi < 2; mi++)
                ldm4(ah[mi], st + (uint32_t)((wm + mi * 16 + a_lr) * PITCHG) + kcol);
            const uint32_t bkcol = (uint32_t)((kk * 16 + b_kh * 8) * 2);
            uint32_t bh[NB][4];
            #pragma unroll
            for (int ni = 0; ni < NB; ni++) {
                uint32_t ro = (uint32_t)((wn + ni * 16 + b_lr + b_nh * 8) * PITCHG) + bkcol;
                ldm4(bh[ni], st + OFF_BH + ro);
            }
            #pragma unroll
            for (int mi = 0; mi < 2; mi++)
                #pragma unroll
                for (int nj = 0; nj < NJ; nj++) {
                    const int ni = nj >> 1, od = (nj & 1) * 2;
                    mma_f16(acc[mi][nj], ah[mi], bh[ni][od], bh[ni][od + 1]);
                }
        }
        __syncthreads();
    }

    const int g = lane >> 2, t = lane & 3;
    // Q columns scaled by 0.125*log2(e) for the exp2-based softmax.
    const float sc = (SPLIT_OUT && n0 < 768) ? 0.180336880111112f : 1.0f;
    #pragma unroll
    for (int mi = 0; mi < 2; mi++)
        #pragma unroll
        for (int nj = 0; nj < NJ; nj++) {
            int row = m0 + wm + mi * 16 + g;
            int col = n0 + wn + nj * 8 + t * 2;
            if (SPLIT_OUT) {
                *reinterpret_cast<uint32_t*>(&Ch[(size_t)row * N + col]) =
                    pack2h(acc[mi][nj][0] * sc, acc[mi][nj][1] * sc);
                *reinterpret_cast<uint32_t*>(&Ch[(size_t)(row + 8) * N + col]) =
                    pack2h(acc[mi][nj][2] * sc, acc[mi][nj][3] * sc);
            } else {
                *reinterpret_cast<float2*>(&C[(size_t)row * N + col]) =
                    make_float2(acc[mi][nj][0], acc[mi][nj][1]);
                *reinterpret_cast<float2*>(&C[(size_t)(row + 8) * N + col]) =
                    make_float2(acc[mi][nj][2], acc[mi][nj][3]);
            }
        }
}

#define QKV_SMEM (3 * ((GBM + 128) * PITCHG))   // 110592
#define OPJ_SMEM (3 * ((GBM + 96) * PITCHG))    // 96768

// ---------------- fp16 causal flash attention, split-KV ----------------
// S = Qh*Kh (1 product), Q pre-scaled by 0.125*log2(e); exp2 softmax;
// O = Ph*Vh (1 product). grid (24 bh, 24 items), 4 KV buffers, 1 barrier/tile.
#define P144 144
#define SQH 0
#define SKV 18432
#define KVSTAGE 18432          // KH 0 | VH 9216
#define ATT_SMEM (SKV + 4 * KVSTAGE)   // 92160

__global__ __launch_bounds__(256, 2)
void attn_mma() {
    extern __shared__ char smc[];
    const uint32_t sb = smem_u32(smc);
    const int tid = threadIdx.x;
    const int lane = tid & 31;
    const int wid = tid >> 5;
    const int bh = blockIdx.x;
    const int4 it = g_items[blockIdx.y];
    const int qb = it.x, kt0 = it.y, kt1 = it.z, hlf = it.w;
    const int b = bh / NUM_HEADS;
    const int h = bh % NUM_HEADS;
    const int wm = wid * 16;
    const int g = lane >> 2, t = lane & 3;

    const size_t qrow0 = (size_t)b * SEQ + (size_t)qb * 128;
    const size_t krow0 = (size_t)b * SEQ;
    const size_t qoff = (size_t)h * DK;
    const size_t koff = 768 + (size_t)h * DK;
    const size_t voff = 1536 + (size_t)h * DK;

    // Q tile (hi fp16), persistent
    #pragma unroll
    for (int l = 0; l < 4; l++) {
        int idx = tid + l * 256;
        int r = idx >> 3, c = idx & 7;
        size_t ga = (qrow0 + r) * D_QKV + qoff + c * 8;
        uint32_t so = (uint32_t)(r * P144 + c * 16);
        cp16(sb + SQH + so, g_qkvh + ga);
    }

    const int ntl = kt1 - kt0;
    auto load_kv = [&](int kt) {
        uint32_t stb = sb + SKV + (uint32_t)(kt & 3) * KVSTAGE;
        #pragma unroll
        for (int l = 0; l < 2; l++) {
            int idx = tid + l * 256;
            int r = idx >> 3, c = idx & 7;
            size_t grow = (krow0 + (size_t)kt * 64 + r) * D_QKV;
            uint32_t so = (uint32_t)(r * P144 + c * 16);
            cp16(stb + so, g_qkvh + grow + koff + c * 8);
            cp16(stb + 9216 + so, g_qkvh + grow + voff + c * 8);
        }
        asm volatile("cp.async.commit_group;" ::: "memory");
    };

    load_kv(kt0);
    if (ntl > 1) load_kv(kt0 + 1);
    if (ntl > 2) load_kv(kt0 + 2);

    float oacc[8][4] = {};
    float m_i[2] = {-INFINITY, -INFINITY};
    float l_i[2] = {0.0f, 0.0f};

    const int a_lr = lane & 15, a_lc = lane >> 4;
    const int b_lr = lane & 7, b_kh = (lane >> 3) & 1, b_nh = lane >> 4;
    const int v_r = lane & 15, v_c = (lane >> 4) * 8;

    for (int j = 0; j < ntl; j++) {
        const int kt = kt0 + j;
        int rem = ntl - 1 - j;
        wait_rem(rem < 2 ? rem : 2);
        __syncthreads();   // publish tile kt from ALL threads; tile kt-1 reads done
        if (j + 3 < ntl) load_kv(kt + 3);   // overwrites (kt-1)&3 — safe now

        const uint32_t stb = sb + SKV + (uint32_t)(kt & 3) * KVSTAGE;
        const bool skip = (kt == 2 * qb + 1) && (wid < 4);

        if (!skip) {
            float sacc[8][4] = {};
            #pragma unroll
            for (int kk = 0; kk < 4; kk++) {
                const uint32_t kcol = (uint32_t)((kk * 16 + a_lc * 8) * 2);
                uint32_t qh[4];
                ldm4(qh, sb + SQH + (uint32_t)((wm + a_lr) * P144) + kcol);
                const uint32_t bkcol = (uint32_t)((kk * 16 + b_kh * 8) * 2);
                #pragma unroll
                for (int np = 0; np < 4; np++) {
                    uint32_t kh[4];
                    ldm4(kh, stb + (uint32_t)((np * 16 + b_lr + b_nh * 8) * P144) + bkcol);
                    mma_f16(sacc[2 * np],     qh, kh[0], kh[1]);
                    mma_f16(sacc[2 * np + 1], qh, kh[2], kh[3]);
                }
            }

            const bool needmask = (kt == 2 * qb && wid < 4) ||
                                  (kt == 2 * qb + 1 && wid >= 4);
            if (needmask) {
                const int grow0 = qb * 128 + wm + g;
                #pragma unroll
                for (int nt = 0; nt < 8; nt++) {
                    const int gcol = kt * 64 + nt * 8 + t * 2;
                    #pragma unroll
                    for (int jj = 0; jj < 4; jj++) {
                        const int row = grow0 + (jj >> 1) * 8;
                        const int col = gcol + (jj & 1);
                        if (col > row) sacc[nt][jj] = -INFINITY;
                    }
                }
            }

            // base-2 online softmax per row-half
            #pragma unroll
            for (int hh = 0; hh < 2; hh++) {
                float rm = -INFINITY;
                #pragma unroll
                for (int nt = 0; nt < 8; nt++)
                    rm = fmaxf(rm, fmaxf(sacc[nt][2 * hh], sacc[nt][2 * hh + 1]));
                rm = fmaxf(rm, __shfl_xor_sync(0xffffffffu, rm, 1));
                rm = fmaxf(rm, __shfl_xor_sync(0xffffffffu, rm, 2));
                float mn = fmaxf(m_i[hh], rm);
                float alpha = exp2f(m_i[hh] - mn);
                float rs = 0.0f;
                #pragma unroll
                for (int nt = 0; nt < 8; nt++) {
                    float p0 = exp2f(sacc[nt][2 * hh] - mn);
                    float p1 = exp2f(sacc[nt][2 * hh + 1] - mn);
                    sacc[nt][2 * hh] = p0;
                    sacc[nt][2 * hh + 1] = p1;
                    rs += p0 + p1;
                }
                rs += __shfl_xor_sync(0xffffffffu, rs, 1);
                rs += __shfl_xor_sync(0xffffffffu, rs, 2);
                l_i[hh] = l_i[hh] * alpha + rs;
                m_i[hh] = mn;
                #pragma unroll
                for (int nt = 0; nt < 8; nt++) {
                    oacc[nt][2 * hh] *= alpha;
                    oacc[nt][2 * hh + 1] *= alpha;
                }
            }

            // O += Ph Vh (1 product)
            #pragma unroll
            for (int ks = 0; ks < 4; ks++) {
                uint32_t ph[4];
                ph[0] = pack2h(sacc[2 * ks][0],     sacc[2 * ks][1]);
                ph[1] = pack2h(sacc[2 * ks][2],     sacc[2 * ks][3]);
                ph[2] = pack2h(sacc[2 * ks + 1][0], sacc[2 * ks + 1][1]);
                ph[3] = pack2h(sacc[2 * ks + 1][2], sacc[2 * ks + 1][3]);
                const uint32_t vrow = (uint32_t)((ks * 16 + v_r) * P144);
                #pragma unroll
                for (int np = 0; np < 4; np++) {
                    uint32_t vh[4];
                    ldm4t(vh, stb + 9216 + vrow + (uint32_t)((np * 16 + v_c) * 2));
                    mma_f16(oacc[2 * np],     ph, vh[0], vh[1]);
                    mma_f16(oacc[2 * np + 1], ph, vh[2], vh[3]);
                }
            }
        }
    }

    const int r0 = wm + g, r1 = wm + g + 8;
    if (hlf < 0) {
        // light item: normalize + write fp16 final
        const float inv0 = 1.0f / l_i[0], inv1 = 1.0f / l_i[1];
        #pragma unroll
        for (int nt = 0; nt < 8; nt++) {
            size_t a0 = (qrow0 + r0) * D_MODEL + qoff + nt * 8 + t * 2;
            size_t a1 = (qrow0 + r1) * D_MODEL + qoff + nt * 8 + t * 2;
            *reinterpret_cast<uint32_t*>(&g_ah[a0]) =
                pack2h(oacc[nt][0] * inv0, oacc[nt][1] * inv0);
            *reinterpret_cast<uint32_t*>(&g_ah[a1]) =
                pack2h(oacc[nt][2] * inv1, oacc[nt][3] * inv1);
        }
    } else {
        // split item: write unnormalized partial O + (m, l)
        const int sidx = (bh * 8 + (qb - 8)) * 2 + hlf;
        float* P = g_part + (size_t)sidx * 8192;
        #pragma unroll
        for (int nt = 0; nt < 8; nt++) {
            const int col = nt * 8 + t * 2;
            *reinterpret_cast<float2*>(&P[r0 * 64 + col]) =
                make_float2(oacc[nt][0], oacc[nt][1]);
            *reinterpret_cast<float2*>(&P[r1 * 64 + col]) =
                make_float2(oacc[nt][2], oacc[nt][3]);
        }
        if (t == 0) {
            g_ml[sidx * 256 + r0 * 2 + 0] = m_i[0];
            g_ml[sidx * 256 + r0 * 2 + 1] = l_i[0];
            g_ml[sidx * 256 + r1 * 2 + 0] = m_i[1];
            g_ml[sidx * 256 + r1 * 2 + 1] = l_i[1];
        }
    }
}

// ---------------- combine split-KV partials ----------------
// grid (8 qb', 24 bh), 1024 threads: thread = one row x 8 cols.
__global__ __launch_bounds__(1024)
void combine_kernel() {
    const int qb2 = blockIdx.x;          // qb = 8 + qb2
    const int bh = blockIdx.y;
    const int b = bh / NUM_HEADS, h = bh % NUM_HEADS;
    const int row = threadIdx.x >> 3;
    const int c0 = (threadIdx.x & 7) * 8;
    const int sidx0 = (bh * 8 + qb2) * 2;
    const float* P0 = g_part + (size_t)sidx0 * 8192;
    const float* P1 = P0 + 8192;
    const float m0 = g_ml[sidx0 * 256 + row * 2 + 0];
    const float l0 = g_ml[sidx0 * 256 + row * 2 + 1];
    const float m1 = g_ml[(sidx0 + 1) * 256 + row * 2 + 0];
    const float l1 = g_ml[(sidx0 + 1) * 256 + row * 2 + 1];
    const float m = fmaxf(m0, m1);
    const float w0 = exp2f(m0 - m), w1 = exp2f(m1 - m);
    const float inv = 1.0f / (l0 * w0 + l1 * w1);

    const size_t orow = ((size_t)b * SEQ + (size_t)(8 + qb2) * 128 + row) * D_MODEL
                        + (size_t)h * DK + c0;
    #pragma unroll
    for (int cc = 0; cc < 8; cc += 4) {
        float4 p0 = *reinterpret_cast<const float4*>(&P0[row * 64 + c0 + cc]);
        float4 p1 = *reinterpret_cast<const float4*>(&P1[row * 64 + c0 + cc]);
        uint2 o;
        o.x = pack2h((p0.x * w0 + p1.x * w1) * inv, (p0.y * w0 + p1.y * w1) * inv);
        o.y = pack2h((p0.z * w0 + p1.z * w1) * inv, (p0.w * w0 + p1.w * w1) * inv);
        *reinterpret_cast<uint2*>(&g_ah[orow + cc]) = o;
    }
}

// ---------------- launch ----------------
extern "C" void kernel_launch(void* const* d_in, const int* in_sizes, int n_in,
                              void* d_out, int out_size) {
    const float* x  = (const float*)d_in[0];
    const float* wq = (const float*)d_in[1];
    const float* wk = (const float*)d_in[2];
    const float* wv = (const float*)d_in[3];
    const float* wo = (const float*)d_in[4];
    float* out = (float*)d_out;

    __half *xh, *qkvh, *ah, *wh;
    cudaGetSymbolAddress((void**)&xh, g_xh);
    cudaGetSymbolAddress((void**)&qkvh, g_qkvh);
    cudaGetSymbolAddress((void**)&ah, g_ah);
    cudaGetSymbolAddress((void**)&wh, g_wh);

    // 1. round x + 4 weights to fp16, ONE launch
    dim3 rgrid((XN / 4 + 255) / 256, 5);
    round5_kernel<<<rgrid, 256>>>(x, wq, wk, wv, wo);

    // 2. fused QKV projection (N = 2304), BK=64, 128x128, 2 CTAs/SM
    cudaFuncSetAttribute((const void*)gemm_mma<128, true>,
                         cudaFuncAttributeMaxDynamicSharedMemorySize, QKV_SMEM);
    cudaFuncSetAttribute((const void*)gemm_mma<96, false>,
                         cudaFuncAttributeMaxDynamicSharedMemorySize, OPJ_SMEM);
    dim3 qkvgrid(D_QKV / 128, MTOT / GBM);   // (18, 32)
    gemm_mma<128, true><<<qkvgrid, 256, QKV_SMEM>>>(xh, wh, nullptr, qkvh,
                                                    MTOT, D_QKV, D_MODEL);

    // 3. split-KV flash attention + separate combine (known-fast)
    cudaFuncSetAttribute(attn_mma, cudaFuncAttributeMaxDynamicSharedMemorySize, ATT_SMEM);
    dim3 agrid(24, 24);   // x = bh, y = work item (heaviest first)
    attn_mma<<<agrid, 256, ATT_SMEM>>>();
    dim3 cgrid(8, 24);
    combine_kernel<<<cgrid, 1024>>>();

    // 4. output projection -> fp32 (1 product), 128x96 tiles, 256 CTAs (86% fill)
    dim3 ogrid(D_MODEL / 96, MTOT / GBM);   // (8, 32)
    gemm_mma<96, false><<<ogrid, 256, OPJ_SMEM>>>(ah, wh + 3 * WN, out, nullptr,
                                                  MTOT, D_MODEL, D_MODEL);
}